// round 14
// baseline (speedup 1.0000x reference)
#include <cuda_runtime.h>
#include <math.h>

#define BB 8
#define CC 64
#define NN 4096
#define KK 32
#define NPTS (BB*NN)          // 32768
#define EPSB 1e-5f
#define NEG_INF (-3.4e38f)
#define FULLM 0xffffffffu

// ---------------- device scratch (static, allocation-free) ----------------
__device__ float g_Pq[NPTS*CC];
__device__ float g_Pk[NPTS*CC];
__device__ float g_Pv[NPTS*CC];
__device__ float g_sq[NPTS];
__device__ int   g_idx[NPTS*KK];
__device__ float g_y1[(size_t)NPTS*CC];
__device__ float g_y2[(size_t)NPTS*CC];
__device__ float g_stats[256];               // [sum1|sumsq1|sum2|sumsq2] x 64ch

// ---------------- zero stats (graph-replay safe; also used as pad launch) ----------------
__global__ void k_zero() { g_stats[threadIdx.x] = 0.f; }

// ---------------- K1: feat projections Pq/Pk/Pv + sq ----------------
__global__ void k_proj(const float* __restrict__ x, const float* __restrict__ wq,
                       const float* __restrict__ wk, const float* __restrict__ wv) {
    extern __shared__ float sm[];
    float* sW = sm;              // 3 * 64*65, layout [w][c*65+o] (transposed, padded)
    float* sf = sm + 3*4160;     // 64*65, layout [p*65+c]
    int t = threadIdx.x;
    int b  = blockIdx.x >> 6;
    int n0 = (blockIdx.x & 63) * 64;
    const float* ws[3] = {wq, wk, wv};
#pragma unroll
    for (int w = 0; w < 3; w++)
#pragma unroll
        for (int s = 0; s < 16; s++) {
            int i = t + 256*s; int o = i >> 6, c = i & 63;
            sW[w*4160 + c*65 + o] = ws[w][i];
        }
    const float* xb = x + (size_t)b*CC*NN;
#pragma unroll
    for (int s = 0; s < 16; s++) {
        int i = t + 256*s; int c = i >> 6, p = i & 63;
        sf[p*65 + c] = xb[c*NN + n0 + p];
    }
    __syncthreads();
    if (t < 64) {
        float s = 0.f;
#pragma unroll
        for (int c = 0; c < 64; c++) { float v = sf[t*65+c]; s += v*v; }
        g_sq[b*NN + n0 + t] = s;
    }
    float* outs[3] = {g_Pq, g_Pk, g_Pv};
#pragma unroll
    for (int w = 0; w < 3; w++)
#pragma unroll
        for (int s = 0; s < 16; s++) {
            int i = t + 256*s; int p = i >> 6, o = i & 63;
            float acc = 0.f;
#pragma unroll
            for (int c = 0; c < 64; c++)
                acc += sf[p*65+c] * sW[w*4160 + c*65 + o];
            outs[w][(size_t)(b*NN + n0 + p)*CC + o] = acc;
        }
}

// ---------------- K2: FUSED distance GEMM + streaming top-32 (v5) ----------------
// 128x128 tiles, 256 threads (16x16), 8x8 micro-tile.
// v5: bank-conflict fix. Thread columns remapped from tx*8..+7 (32B stride,
// 4-way LDS conflict on B loads) to {tx*4..+3, 64+tx*4..+3} (16B stride,
// 2-way only). B-fragment crossbar cost drops 4x -> 2 phases; FFMA becomes
// the binding pipe. Lists stay in smem (v4). Strictly-greater admission +
// ascending-column order matches top_k tie semantics (set equality).
__global__ void __launch_bounds__(256, 2)
k_dist_topk(const float* __restrict__ x) {
    extern __shared__ float sm[];
    float* As  = sm;                    // [k*132 + r]  64 x 128 (+pad)
    float* Bs  = sm + 64*132;           // [k*132 + m]  64 x 128 (+pad)
    float* sqs = Bs + 64*132;           // [128]
    float* sLv = sqs + 128;             // [128 rows][32 lanes]
    int*   sLi = (int*)(sLv + 128*32);  // [128 rows][32 lanes]
    int t  = threadIdx.x;
    int b  = blockIdx.y;
    int n0 = blockIdx.x * 128;
    const float* xb = x + (size_t)b*CC*NN;

    int tx = t & 15, ty = t >> 4;
    int lane = t & 31, w = t >> 5;

    // init lists
#pragma unroll
    for (int s = 0; s < 16; s++) { sLv[s*256 + t] = NEG_INF; sLi[s*256 + t] = 0; }

    // load A tile (128 rows x 64 ch), layout [k][r], float4
#pragma unroll
    for (int s = 0; s < 8; s++) {
        int i4 = (s*256 + t) * 4; int c = i4 >> 7, r = i4 & 127;
        *(float4*)(As + c*132 + r) = *(const float4*)(xb + c*NN + n0 + r);
    }

    for (int tile = 0; tile < 32; tile++) {
        int m0 = tile * 128;
        float sqld = (t < 128) ? g_sq[b*NN + m0 + t] : 0.f;   // overlap with B load
        __syncthreads();
#pragma unroll
        for (int s = 0; s < 8; s++) {
            int i4 = (s*256 + t) * 4; int c = i4 >> 7, m = i4 & 127;
            *(float4*)(Bs + c*132 + m) = *(const float4*)(xb + c*NN + m0 + m);
        }
        if (t < 128) sqs[t] = sqld;
        __syncthreads();

        // GEMM: rows ty*8..+7, cols {tx*4..+3, 64+tx*4..+3}
        float acc[8][8];
#pragma unroll
        for (int i = 0; i < 8; i++)
#pragma unroll
            for (int j = 0; j < 8; j++) acc[i][j] = 0.f;
#pragma unroll 4
        for (int k = 0; k < 64; k++) {
            float4 a0 = *(const float4*)(As + k*132 + ty*8);
            float4 a1 = *(const float4*)(As + k*132 + ty*8 + 4);
            float4 b0 = *(const float4*)(Bs + k*132 + tx*4);
            float4 b1 = *(const float4*)(Bs + k*132 + 64 + tx*4);
            float av[8] = {a0.x,a0.y,a0.z,a0.w,a1.x,a1.y,a1.z,a1.w};
            float bv[8] = {b0.x,b0.y,b0.z,b0.w,b1.x,b1.y,b1.z,b1.w};
#pragma unroll
            for (int i = 0; i < 8; i++)
#pragma unroll
                for (int j = 0; j < 8; j++) acc[i][j] += av[i]*bv[j];
        }

        // fold score = 2*acc - sq[m]; per-acc-row max
        float4 sq0 = *(const float4*)(sqs + tx*4);
        float4 sq1 = *(const float4*)(sqs + 64 + tx*4);
        float sqv[8] = {sq0.x,sq0.y,sq0.z,sq0.w,sq1.x,sq1.y,sq1.z,sq1.w};
        float rowmax[8];
#pragma unroll
        for (int i = 0; i < 8; i++) {
            float mx = NEG_INF;
#pragma unroll
            for (int j = 0; j < 8; j++) {
                acc[i][j] = fmaf(2.f, acc[i][j], -sqv[j]);
                mx = fmaxf(mx, acc[i][j]);
            }
            rowmax[i] = mx;
        }

        // register scan over 16 rows per warp; lists staged from smem
#pragma unroll
        for (int r16 = 0; r16 < 16; r16++) {
            const int i = r16 & 7;
            bool owner = ((lane < 16) == (r16 < 8));
            int rl = w*16 + r16;
            float lv = sLv[rl*32 + lane];
            float thr = __shfl_sync(FULLM, lv, 31);
            unsigned pmask = __ballot_sync(FULLM, (owner ? rowmax[i] : NEG_INF) > thr);
            if (pmask) {
                int li = sLi[rl*32 + lane];
                do {
                    int src = __ffs(pmask) - 1; pmask &= pmask - 1;
                    int sc4 = (src & 15) << 2;
#pragma unroll
                    for (int j = 0; j < 8; j++) {
                        float vv = __shfl_sync(FULLM, acc[i][j], src);
                        if (vv > thr) {   // warp-uniform (vv, thr broadcast)
                            int vi = m0 + ((j < 4) ? (sc4 + j) : (64 + sc4 + j - 4));
                            int pos = __popc(__ballot_sync(FULLM, lv >= vv));
                            float sv = __shfl_up_sync(FULLM, lv, 1);
                            int   si = __shfl_up_sync(FULLM, li, 1);
                            if (lane > pos)       { lv = sv; li = si; }
                            else if (lane == pos) { lv = vv; li = vi; }
                            thr = __shfl_sync(FULLM, lv, 31);
                        }
                    }
                } while (pmask);
                sLv[rl*32 + lane] = lv;
                sLi[rl*32 + lane] = li;
            }
        }
    }
    __syncthreads();
    // emit: lane l = rank l of each owned row
#pragma unroll
    for (int r16 = 0; r16 < 16; r16++) {
        int rl = w*16 + r16;
        int row = b*NN + n0 + rl;
        g_idx[(size_t)row*KK + lane] = sLi[rl*32 + lane];
    }
}

// ---------------- K4: attention via gathered projections + residual + BN1 stats ----------------
__global__ void k_attn(const float* __restrict__ x) {
    __shared__ int   sidx[2][32];
    __shared__ float sred[128];
    int t  = threadIdx.x;
    int pt = t >> 6;
    int c  = t & 63;
    int P  = blockIdx.x*2 + pt;        // global row = b*4096 + n
    int b  = P >> 12;
    int n  = P & 4095;
    if (c < 32) sidx[pt][c] = g_idx[(size_t)P*KK + c];
    __syncthreads();
    size_t rb = (size_t)P*CC;
    float qc  = g_Pq[rb + c];
    float pkn = g_Pk[rb + c];
    float pvn = g_Pv[rb + c];
    size_t bbase = (size_t)b << 12;
    float e[32];
#pragma unroll
    for (int j = 0; j < 32; j++) {
        int m = sidx[pt][j];
        float p = qc * (g_Pk[(bbase + m)*CC + c] - pkn);
        p += __shfl_xor_sync(FULLM, p, 8);
        p += __shfl_xor_sync(FULLM, p, 4);
        p += __shfl_xor_sync(FULLM, p, 2);
        p += __shfl_xor_sync(FULLM, p, 1);
        e[j] = p * 0.25f;                     // / sqrt(D), D=16
    }
    float mx = e[0];
#pragma unroll
    for (int j=1;j<32;j++) mx = fmaxf(mx, e[j]);
    float ssum = 0.f;
#pragma unroll
    for (int j=0;j<32;j++){ e[j] = __expf(e[j]-mx); ssum += e[j]; }
    float inv = 1.f/ssum;
    float acc = 0.f;
#pragma unroll
    for (int j=0;j<32;j++){
        int m = sidx[pt][j];
        acc += e[j] * g_Pv[(bbase + m)*CC + c];
    }
    float outv = acc*inv - pvn;
    float y = x[(size_t)b*CC*NN + (size_t)c*NN + n] + outv;
    g_y1[rb + c] = y;
    sred[t] = y; __syncthreads();
    if (t < 64) atomicAdd(&g_stats[c], sred[t] + sred[t+64]);
    __syncthreads();
    sred[t] = y*y; __syncthreads();
    if (t < 64) atomicAdd(&g_stats[64+c], sred[t] + sred[t+64]);
}

// ---------------- K6: BN1 apply + MLP (fused, weights resident) + BN2 stats ----------------
__global__ void __launch_bounds__(256, 1)
k_mlp(const float* __restrict__ w1, const float* __restrict__ w2,
      const float* __restrict__ g1, const float* __restrict__ b1) {
    extern __shared__ float sm[];
    float* sW1  = sm;                      // [c*257+o]
    float* sW2  = sm + 16448;              // [c*257+o]
    float* sf1  = sm + 2*16448;            // [p*65+c]
    float* shid = sm + 2*16448 + 2080;     // [p*256+o]
    __shared__ float sred[256];
    int t = threadIdx.x;
    int rowbase = blockIdx.x * 32;
#pragma unroll
    for (int s = 0; s < 64; s++) {
        int i = t + 256*s; int o = i >> 6, c = i & 63;
        sW1[c*257 + o] = w1[i];
    }
#pragma unroll
    for (int s = 0; s < 64; s++) {
        int i = t + 256*s; int c = i >> 8, o = i & 255;
        sW2[c*257 + o] = w2[i];
    }
    const float invN = 1.f/32768.f;
#pragma unroll
    for (int s = 0; s < 8; s++) {
        int i = t + 256*s; int p = i >> 6, c = i & 63;
        float mu  = g_stats[c]*invN;
        float var = g_stats[64+c]*invN - mu*mu;
        float v = g_y1[(size_t)(rowbase+p)*CC + c];
        sf1[p*65 + c] = (v - mu)*rsqrtf(var + EPSB)*g1[c] + b1[c];
    }
    __syncthreads();
    {
        int o = t;
#pragma unroll
        for (int pb = 0; pb < 4; pb++) {
            float acc[8];
#pragma unroll
            for (int p=0;p<8;p++) acc[p]=0.f;
#pragma unroll
            for (int cc2 = 0; cc2 < 64; cc2++) {
                float w = sW1[cc2*257 + o];
#pragma unroll
                for (int p=0;p<8;p++) acc[p] += sf1[(pb*8+p)*65 + cc2]*w;
            }
#pragma unroll
            for (int p=0;p<8;p++){
                float h = acc[p];
                shid[(pb*8+p)*256 + o] = h > 0.f ? h : 0.2f*h;
            }
        }
    }
    __syncthreads();
    {
        int c = t & 63; int pg = t >> 6;
        float acc[8];
#pragma unroll
        for (int q=0;q<8;q++) acc[q]=0.f;
#pragma unroll 16
        for (int oo = 0; oo < 256; oo++) {
            float w = sW2[c*257 + oo];
#pragma unroll
            for (int q=0;q<8;q++) acc[q] += shid[(pg*8+q)*256 + oo]*w;
        }
        float psum=0.f, psq=0.f;
#pragma unroll
        for (int q=0;q<8;q++){
            int p = pg*8+q;
            float y = sf1[p*65 + c] + acc[q];
            g_y2[(size_t)(rowbase+p)*CC + c] = y;
            psum += y; psq += y*y;
        }
        sred[t]=psum; __syncthreads();
        if (t<64){
            float s2=sred[t]+sred[t+64]+sred[t+128]+sred[t+192];
            atomicAdd(&g_stats[128+t], s2);
        }
        __syncthreads();
        sred[t]=psq; __syncthreads();
        if (t<64){
            float s2=sred[t]+sred[t+64]+sred[t+128]+sred[t+192];
            atomicAdd(&g_stats[192+t], s2);
        }
    }
}

// ---------------- K7: BN2 apply + transpose to (B,C,N) ----------------
__global__ void k_final(float* __restrict__ out, const float* __restrict__ g2,
                        const float* __restrict__ b2) {
    __shared__ float tile[64*65];
    int t = threadIdx.x;
    int b  = blockIdx.x >> 6;
    int n0 = (blockIdx.x & 63)*64;
    const float invN = 1.f/32768.f;
#pragma unroll
    for (int s = 0; s < 16; s++) {
        int i = t + 256*s; int p = i >> 6, c = i & 63;
        float mu  = g_stats[128+c]*invN;
        float var = g_stats[192+c]*invN - mu*mu;
        float v = g_y2[(size_t)(b*NN + n0 + p)*CC + c];
        tile[c*65 + p] = (v-mu)*rsqrtf(var+EPSB)*g2[c] + b2[c];
    }
    __syncthreads();
#pragma unroll
    for (int s = 0; s < 16; s++) {
        int i = t + 256*s; int c = i >> 6, p = i & 63;
        out[(size_t)b*CC*NN + (size_t)c*NN + n0 + p] = tile[c*65 + p];
    }
}

// ---------------- launch ----------------
extern "C" void kernel_launch(void* const* d_in, const int* in_sizes, int n_in,
                              void* d_out, int out_size) {
    const float* x  = (const float*)d_in[0];
    const float* wq = (const float*)d_in[1];
    const float* wk = (const float*)d_in[2];
    const float* wv = (const float*)d_in[3];
    const float* w1 = (const float*)d_in[4];
    const float* w2 = (const float*)d_in[5];
    const float* g1 = (const float*)d_in[6];
    const float* b1 = (const float*)d_in[7];
    const float* g2 = (const float*)d_in[8];
    const float* b2 = (const float*)d_in[9];
    float* out = (float*)d_out;

    const int PROJ_SMEM = 4*4160*4;                          // 66560
    const int DT_SMEM   = (2*64*132 + 128 + 2*128*32)*4;     // 100864
    const int MLP_SMEM  = (2*16448 + 2080 + 32*256)*4;       // 172672
    cudaFuncSetAttribute(k_proj,      cudaFuncAttributeMaxDynamicSharedMemorySize, PROJ_SMEM);
    cudaFuncSetAttribute(k_dist_topk, cudaFuncAttributeMaxDynamicSharedMemorySize, DT_SMEM);
    cudaFuncSetAttribute(k_mlp,       cudaFuncAttributeMaxDynamicSharedMemorySize, MLP_SMEM);

    k_zero<<<1, 256>>>();                             // launch 1
    k_proj<<<512, 256, PROJ_SMEM>>>(x, wq, wk, wv);   // launch 2
    k_zero<<<1, 256>>>();                             // launch 3 (pad for ncu)
    k_dist_topk<<<dim3(32, 8), 256, DT_SMEM>>>(x);    // launch 4 -> profiled
    k_attn<<<NPTS/2, 128>>>(x);
    k_mlp<<<NPTS/32, 256, MLP_SMEM>>>(w1, w2, g1, b1);
    k_final<<<512, 256>>>(out, g2, b2);
}

// round 15
// speedup vs baseline: 1.5399x; 1.5399x over previous
#include <cuda_runtime.h>
#include <math.h>

#define BB 8
#define CC 64
#define NN 4096
#define KK 32
#define NPTS (BB*NN)          // 32768
#define EPSB 1e-5f
#define NEG_INF (-3.4e38f)
#define FULLM 0xffffffffu

// ---------------- device scratch (static, allocation-free) ----------------
__device__ float g_Pq[NPTS*CC];
__device__ float g_Pk[NPTS*CC];
__device__ float g_Pv[NPTS*CC];
__device__ float g_sq[NPTS];
__device__ float g_score[(size_t)NPTS*NN];   // 512 MB ranking scores 2*G - sq[m]
__device__ int   g_idx[NPTS*KK];
__device__ float g_y1[(size_t)NPTS*CC];
__device__ float g_y2[(size_t)NPTS*CC];
__device__ float g_stats[256];               // [sum1|sumsq1|sum2|sumsq2] x 64ch

// ---------------- zero stats (graph-replay safe; also pad launch) ----------------
__global__ void k_zero() { g_stats[threadIdx.x] = 0.f; }

// ---------------- K1: feat projections Pq/Pk/Pv + sq ----------------
__global__ void k_proj(const float* __restrict__ x, const float* __restrict__ wq,
                       const float* __restrict__ wk, const float* __restrict__ wv) {
    extern __shared__ float sm[];
    float* sW = sm;              // 3 * 64*65, layout [w][c*65+o] (transposed, padded)
    float* sf = sm + 3*4160;     // 64*65, layout [p*65+c]
    int t = threadIdx.x;
    int b  = blockIdx.x >> 6;
    int n0 = (blockIdx.x & 63) * 64;
    const float* ws[3] = {wq, wk, wv};
#pragma unroll
    for (int w = 0; w < 3; w++)
#pragma unroll
        for (int s = 0; s < 16; s++) {
            int i = t + 256*s; int o = i >> 6, c = i & 63;
            sW[w*4160 + c*65 + o] = ws[w][i];
        }
    const float* xb = x + (size_t)b*CC*NN;
#pragma unroll
    for (int s = 0; s < 16; s++) {
        int i = t + 256*s; int c = i >> 6, p = i & 63;
        sf[p*65 + c] = xb[c*NN + n0 + p];
    }
    __syncthreads();
    if (t < 64) {
        float s = 0.f;
#pragma unroll
        for (int c = 0; c < 64; c++) { float v = sf[t*65+c]; s += v*v; }
        g_sq[b*NN + n0 + t] = s;
    }
    float* outs[3] = {g_Pq, g_Pk, g_Pv};
#pragma unroll
    for (int w = 0; w < 3; w++)
#pragma unroll
        for (int s = 0; s < 16; s++) {
            int i = t + 256*s; int p = i >> 6, o = i & 63;
            float acc = 0.f;
#pragma unroll
            for (int c = 0; c < 64; c++)
                acc += sf[p*65+c] * sW[w*4160 + c*65 + o];
            outs[w][(size_t)(b*NN + n0 + p)*CC + o] = acc;
        }
}

// ---------------- K2: symmetric distance-score GEMM (bank-conflict-fixed) ----------------
// s[n][m] = 2*dot(f_n,f_m) - sq[m] (row-constant -sq[n] dropped; rank-invariant).
// grid (32,32,8), by<=bx only; writes tile + mirrored tile. 8x8 micro-tile with
// B columns {tx*4..+3, 64+tx*4..+3} (16B stride -> 2-way LDS conflict max,
// vs 4-way at the old tx*8 mapping). float4 tile loads.
__global__ void __launch_bounds__(256, 2)
k_dist(const float* __restrict__ x) {
    int bx = blockIdx.x, by = blockIdx.y, b = blockIdx.z;
    if (by > bx) return;
    extern __shared__ float sm[];
    float* As = sm;              // [k*132 + i] 64 x 128 (+pad)
    float* Bs = sm + 64*132;
    int n0 = by*128, m0 = bx*128;
    const float* xb = x + (size_t)b*CC*NN;   // x is [c][n] = featT already
    int t = threadIdx.x;
#pragma unroll
    for (int s = 0; s < 8; s++) {
        int i4 = (s*256 + t) * 4; int k = i4 >> 7, i = i4 & 127;
        *(float4*)(As + k*132 + i) = *(const float4*)(xb + k*NN + n0 + i);
        *(float4*)(Bs + k*132 + i) = *(const float4*)(xb + k*NN + m0 + i);
    }
    __syncthreads();
    int tx = t & 15, ty = t >> 4;
    float acc[8][8];
#pragma unroll
    for (int i=0;i<8;i++)
#pragma unroll
        for (int j=0;j<8;j++) acc[i][j]=0.f;
#pragma unroll 4
    for (int k = 0; k < 64; k++) {
        float4 a0 = *(const float4*)(As + k*132 + ty*8);
        float4 a1 = *(const float4*)(As + k*132 + ty*8 + 4);
        float4 b0 = *(const float4*)(Bs + k*132 + tx*4);
        float4 b1 = *(const float4*)(Bs + k*132 + 64 + tx*4);
        float av[8] = {a0.x,a0.y,a0.z,a0.w,a1.x,a1.y,a1.z,a1.w};
        float bv[8] = {b0.x,b0.y,b0.z,b0.w,b1.x,b1.y,b1.z,b1.w};
#pragma unroll
        for (int i=0;i<8;i++)
#pragma unroll
            for (int j=0;j<8;j++) acc[i][j] += av[i]*bv[j];
    }
    const float* sqb = g_sq + b*NN;
    float sqm[8], sqn[8];
#pragma unroll
    for (int j=0;j<4;j++) { sqm[j]   = sqb[m0 + tx*4 + j];
                            sqm[j+4] = sqb[m0 + 64 + tx*4 + j]; }
#pragma unroll
    for (int i=0;i<8;i++) sqn[i] = sqb[n0 + ty*8 + i];
    float* base = g_score + (size_t)b*NN*NN;
#pragma unroll
    for (int i=0;i<8;i++) {
        int row = n0 + ty*8 + i;
        float4 v0, v1;
        v0.x = 2.f*acc[i][0]-sqm[0]; v0.y = 2.f*acc[i][1]-sqm[1];
        v0.z = 2.f*acc[i][2]-sqm[2]; v0.w = 2.f*acc[i][3]-sqm[3];
        v1.x = 2.f*acc[i][4]-sqm[4]; v1.y = 2.f*acc[i][5]-sqm[5];
        v1.z = 2.f*acc[i][6]-sqm[6]; v1.w = 2.f*acc[i][7]-sqm[7];
        *(float4*)(base + (size_t)row*NN + m0 + tx*4)      = v0;
        *(float4*)(base + (size_t)row*NN + m0 + 64 + tx*4) = v1;
    }
    if (bx != by) {
#pragma unroll
        for (int j=0;j<8;j++) {
            int rowT = m0 + ((j<4) ? (tx*4 + j) : (64 + tx*4 + j - 4));
            float* d = base + (size_t)rowT*NN + n0 + ty*8;
            float4 v0, v1;
            v0.x = 2.f*acc[0][j]-sqn[0]; v0.y = 2.f*acc[1][j]-sqn[1];
            v0.z = 2.f*acc[2][j]-sqn[2]; v0.w = 2.f*acc[3][j]-sqn[3];
            v1.x = 2.f*acc[4][j]-sqn[4]; v1.y = 2.f*acc[5][j]-sqn[5];
            v1.z = 2.f*acc[6][j]-sqn[6]; v1.w = 2.f*acc[7][j]-sqn[7];
            *(float4*)(d)   = v0;
            *(float4*)(d+4) = v1;
        }
    }
}

// ---------------- K3: top-32 via hierarchical 3-level radix select ----------------
// (R5 version: measured 453us.) Level 1: bits 31:21 over the row; level 2:
// bits 20:10; level 3: bits 9:0. Survivors after L3 are exact float ties ->
// lowest-index pick. No serialized argmax rounds.
__device__ __forceinline__ unsigned fkey(float f) {
    unsigned u = __float_as_uint(f);
    return u ^ ((u & 0x80000000u) ? 0xFFFFFFFFu : 0x80000000u);
}

__device__ __forceinline__ void scan2048(const unsigned* shist, int target, int t,
                                         unsigned lane, unsigned w, unsigned* wsum,
                                         int* s_bstar, int* s_before) {
    unsigned part = 0, hloc[8];
#pragma unroll
    for (int i = 0; i < 8; i++) { hloc[i] = shist[2047 - (t*8 + i)]; part += hloc[i]; }
    unsigned val = part;
#pragma unroll
    for (int off = 1; off < 32; off <<= 1) {
        unsigned nv = __shfl_up_sync(FULLM, val, off);
        if (lane >= off) val += nv;
    }
    if (lane == 31) wsum[w] = val;
    __syncthreads();
    unsigned woff = 0;
#pragma unroll
    for (int i = 0; i < 8; i++) woff += (i < (int)w) ? wsum[i] : 0u;
    unsigned incl = val + woff;
    unsigned excl = incl - part;
    if (excl < (unsigned)target && incl >= (unsigned)target) {
        unsigned acc = excl;
#pragma unroll
        for (int i = 0; i < 8; i++) {
            if (acc + hloc[i] >= (unsigned)target) {
                *s_bstar = 2047 - (t*8 + i); *s_before = (int)acc; break;
            }
            acc += hloc[i];
        }
    }
    __syncthreads();
}

__global__ void __launch_bounds__(256) k_topk() {
    __shared__ unsigned shist[2048];
    __shared__ float bval[2][1024];
    __shared__ int   bidx[2][1024];
    __shared__ unsigned wsum[8];
    __shared__ int s_bstar, s_before, s_cnt, s_emit, s_win;

    int t = threadIdx.x;
    unsigned lane = t & 31, w = t >> 5;
    size_t row = blockIdx.x;
    const float4* src = (const float4*)(g_score + row*(size_t)NN);

#pragma unroll
    for (int i = 0; i < 8; i++) shist[t + 256*i] = 0u;
    if (t == 0) { s_emit = 0; s_cnt = 0; }
    __syncthreads();

    float4 q[4];
#pragma unroll
    for (int j = 0; j < 4; j++) q[j] = src[j*256 + t];

#pragma unroll
    for (int j = 0; j < 4; j++) {
        atomicAdd(&shist[fkey(q[j].x) >> 21], 1u);
        atomicAdd(&shist[fkey(q[j].y) >> 21], 1u);
        atomicAdd(&shist[fkey(q[j].z) >> 21], 1u);
        atomicAdd(&shist[fkey(q[j].w) >> 21], 1u);
    }
    __syncthreads();
    scan2048(shist, KK, t, lane, w, wsum, &s_bstar, &s_before);
    int bstar = s_bstar;
    int need = KK - s_before;
    int* rowidx = g_idx + row*KK;

#pragma unroll
    for (int j = 0; j < 4; j++) {
        float vv[4] = {q[j].x, q[j].y, q[j].z, q[j].w};
#pragma unroll
        for (int e = 0; e < 4; e++) {
            int bin = (int)(fkey(vv[e]) >> 21);
            if (bin > bstar) {
                rowidx[atomicAdd(&s_emit, 1)] = 4*(j*256 + t) + e;
            } else if (bin == bstar) {
                int p = atomicAdd(&s_cnt, 1);
                if (p < 1024) { bval[0][p] = vv[e]; bidx[0][p] = 4*(j*256 + t) + e; }
            }
        }
    }
    __syncthreads();
    int C = s_cnt; if (C > 1024) C = 1024;
    int cur = 0;

    for (int lvl = 0; lvl < 2 && C > need; lvl++) {
        int shift = (lvl == 0) ? 10 : 0;
        unsigned msk = (lvl == 0) ? 0x7FFu : 0x3FFu;
#pragma unroll
        for (int i = 0; i < 8; i++) shist[t + 256*i] = 0u;
        if (t == 0) s_cnt = 0;
        __syncthreads();
        for (int i = t; i < C; i += 256)
            atomicAdd(&shist[(fkey(bval[cur][i]) >> shift) & msk], 1u);
        __syncthreads();
        scan2048(shist, need, t, lane, w, wsum, &s_bstar, &s_before);
        int b2 = s_bstar, before2 = s_before;
        for (int i = t; i < C; i += 256) {
            int bin = (int)((fkey(bval[cur][i]) >> shift) & msk);
            if (bin > b2) {
                rowidx[atomicAdd(&s_emit, 1)] = bidx[cur][i];
            } else if (bin == b2) {
                int p = atomicAdd(&s_cnt, 1);
                bval[cur^1][p] = bval[cur][i]; bidx[cur^1][p] = bidx[cur][i];
            }
        }
        __syncthreads();
        need -= before2;
        C = s_cnt;
        cur ^= 1;
    }

    if (C == need) {
        for (int i = t; i < C; i += 256)
            rowidx[atomicAdd(&s_emit, 1)] = bidx[cur][i];
    } else {
        for (int r = 0; r < need; r++) {
            int li = 0x7fffffff;
            for (int i = t; i < C; i += 256) li = min(li, bidx[cur][i]);
#pragma unroll
            for (int off = 16; off > 0; off >>= 1)
                li = min(li, __shfl_down_sync(FULLM, li, off));
            if (lane == 0) ((int*)wsum)[w] = li;
            __syncthreads();
            if (t == 0) {
                int m = ((int*)wsum)[0];
#pragma unroll
                for (int j = 1; j < 8; j++) m = min(m, ((int*)wsum)[j]);
                rowidx[atomicAdd(&s_emit, 1)] = m;
                s_win = m;
            }
            __syncthreads();
            for (int i = t; i < C; i += 256)
                if (bidx[cur][i] == s_win) bidx[cur][i] = 0x7fffffff;
            __syncthreads();
        }
    }
}

// ---------------- K4: attention via gathered projections + residual + BN1 stats ----------------
__global__ void k_attn(const float* __restrict__ x) {
    __shared__ int   sidx[2][32];
    __shared__ float sred[128];
    int t  = threadIdx.x;
    int pt = t >> 6;
    int c  = t & 63;
    int P  = blockIdx.x*2 + pt;        // global row = b*4096 + n
    int b  = P >> 12;
    int n  = P & 4095;
    if (c < 32) sidx[pt][c] = g_idx[(size_t)P*KK + c];
    __syncthreads();
    size_t rb = (size_t)P*CC;
    float qc  = g_Pq[rb + c];
    float pkn = g_Pk[rb + c];
    float pvn = g_Pv[rb + c];
    size_t bbase = (size_t)b << 12;
    float e[32];
#pragma unroll
    for (int j = 0; j < 32; j++) {
        int m = sidx[pt][j];
        float p = qc * (g_Pk[(bbase + m)*CC + c] - pkn);
        p += __shfl_xor_sync(FULLM, p, 8);
        p += __shfl_xor_sync(FULLM, p, 4);
        p += __shfl_xor_sync(FULLM, p, 2);
        p += __shfl_xor_sync(FULLM, p, 1);
        e[j] = p * 0.25f;                     // / sqrt(D), D=16
    }
    float mx = e[0];
#pragma unroll
    for (int j=1;j<32;j++) mx = fmaxf(mx, e[j]);
    float ssum = 0.f;
#pragma unroll
    for (int j=0;j<32;j++){ e[j] = __expf(e[j]-mx); ssum += e[j]; }
    float inv = 1.f/ssum;
    float acc = 0.f;
#pragma unroll
    for (int j=0;j<32;j++){
        int m = sidx[pt][j];
        acc += e[j] * g_Pv[(bbase + m)*CC + c];
    }
    float outv = acc*inv - pvn;
    float y = x[(size_t)b*CC*NN + (size_t)c*NN + n] + outv;
    g_y1[rb + c] = y;
    sred[t] = y; __syncthreads();
    if (t < 64) atomicAdd(&g_stats[c], sred[t] + sred[t+64]);
    __syncthreads();
    sred[t] = y*y; __syncthreads();
    if (t < 64) atomicAdd(&g_stats[64+c], sred[t] + sred[t+64]);
}

// ---------------- K6: BN1 apply + MLP (fused, weights resident) + BN2 stats ----------------
__global__ void __launch_bounds__(256, 1)
k_mlp(const float* __restrict__ w1, const float* __restrict__ w2,
      const float* __restrict__ g1, const float* __restrict__ b1) {
    extern __shared__ float sm[];
    float* sW1  = sm;                      // [c*257+o]
    float* sW2  = sm + 16448;              // [c*257+o]
    float* sf1  = sm + 2*16448;            // [p*65+c]
    float* shid = sm + 2*16448 + 2080;     // [p*256+o]
    __shared__ float sred[256];
    int t = threadIdx.x;
    int rowbase = blockIdx.x * 32;
#pragma unroll
    for (int s = 0; s < 64; s++) {
        int i = t + 256*s; int o = i >> 6, c = i & 63;
        sW1[c*257 + o] = w1[i];
    }
#pragma unroll
    for (int s = 0; s < 64; s++) {
        int i = t + 256*s; int c = i >> 8, o = i & 255;
        sW2[c*257 + o] = w2[i];
    }
    const float invN = 1.f/32768.f;
#pragma unroll
    for (int s = 0; s < 8; s++) {
        int i = t + 256*s; int p = i >> 6, c = i & 63;
        float mu  = g_stats[c]*invN;
        float var = g_stats[64+c]*invN - mu*mu;
        float v = g_y1[(size_t)(rowbase+p)*CC + c];
        sf1[p*65 + c] = (v - mu)*rsqrtf(var + EPSB)*g1[c] + b1[c];
    }
    __syncthreads();
    {
        int o = t;
#pragma unroll
        for (int pb = 0; pb < 4; pb++) {
            float acc[8];
#pragma unroll
            for (int p=0;p<8;p++) acc[p]=0.f;
#pragma unroll
            for (int cc2 = 0; cc2 < 64; cc2++) {
                float w = sW1[cc2*257 + o];
#pragma unroll
                for (int p=0;p<8;p++) acc[p] += sf1[(pb*8+p)*65 + cc2]*w;
            }
#pragma unroll
            for (int p=0;p<8;p++){
                float h = acc[p];
                shid[(pb*8+p)*256 + o] = h > 0.f ? h : 0.2f*h;
            }
        }
    }
    __syncthreads();
    {
        int c = t & 63; int pg = t >> 6;
        float acc[8];
#pragma unroll
        for (int q=0;q<8;q++) acc[q]=0.f;
#pragma unroll 16
        for (int oo = 0; oo < 256; oo++) {
            float w = sW2[c*257 + oo];
#pragma unroll
            for (int q=0;q<8;q++) acc[q] += shid[(pg*8+q)*256 + oo]*w;
        }
        float psum=0.f, psq=0.f;
#pragma unroll
        for (int q=0;q<8;q++){
            int p = pg*8+q;
            float y = sf1[p*65 + c] + acc[q];
            g_y2[(size_t)(rowbase+p)*CC + c] = y;
            psum += y; psq += y*y;
        }
        sred[t]=psum; __syncthreads();
        if (t<64){
            float s2=sred[t]+sred[t+64]+sred[t+128]+sred[t+192];
            atomicAdd(&g_stats[128+t], s2);
        }
        __syncthreads();
        sred[t]=psq; __syncthreads();
        if (t<64){
            float s2=sred[t]+sred[t+64]+sred[t+128]+sred[t+192];
            atomicAdd(&g_stats[192+t], s2);
        }
    }
}

// ---------------- K7: BN2 apply + transpose to (B,C,N) ----------------
__global__ void k_final(float* __restrict__ out, const float* __restrict__ g2,
                        const float* __restrict__ b2) {
    __shared__ float tile[64*65];
    int t = threadIdx.x;
    int b  = blockIdx.x >> 6;
    int n0 = (blockIdx.x & 63)*64;
    const float invN = 1.f/32768.f;
#pragma unroll
    for (int s = 0; s < 16; s++) {
        int i = t + 256*s; int p = i >> 6, c = i & 63;
        float mu  = g_stats[128+c]*invN;
        float var = g_stats[192+c]*invN - mu*mu;
        float v = g_y2[(size_t)(b*NN + n0 + p)*CC + c];
        tile[c*65 + p] = (v-mu)*rsqrtf(var+EPSB)*g2[c] + b2[c];
    }
    __syncthreads();
#pragma unroll
    for (int s = 0; s < 16; s++) {
        int i = t + 256*s; int c = i >> 6, p = i & 63;
        out[(size_t)b*CC*NN + (size_t)c*NN + n0 + p] = tile[c*65 + p];
    }
}

// ---------------- launch ----------------
extern "C" void kernel_launch(void* const* d_in, const int* in_sizes, int n_in,
                              void* d_out, int out_size) {
    const float* x  = (const float*)d_in[0];
    const float* wq = (const float*)d_in[1];
    const float* wk = (const float*)d_in[2];
    const float* wv = (const float*)d_in[3];
    const float* w1 = (const float*)d_in[4];
    const float* w2 = (const float*)d_in[5];
    const float* g1 = (const float*)d_in[6];
    const float* b1 = (const float*)d_in[7];
    const float* g2 = (const float*)d_in[8];
    const float* b2 = (const float*)d_in[9];
    float* out = (float*)d_out;

    const int PROJ_SMEM = 4*4160*4;        // 66560
    const int DIST_SMEM = 2*64*132*4;      // 67584
    const int MLP_SMEM  = (2*16448 + 2080 + 32*256)*4;   // 172672
    cudaFuncSetAttribute(k_proj, cudaFuncAttributeMaxDynamicSharedMemorySize, PROJ_SMEM);
    cudaFuncSetAttribute(k_dist, cudaFuncAttributeMaxDynamicSharedMemorySize, DIST_SMEM);
    cudaFuncSetAttribute(k_mlp,  cudaFuncAttributeMaxDynamicSharedMemorySize, MLP_SMEM);

    k_zero<<<1, 256>>>();                                 // launch 1
    k_proj<<<512, 256, PROJ_SMEM>>>(x, wq, wk, wv);       // launch 2
    k_zero<<<1, 256>>>();                                 // launch 3 (pad for ncu)
    k_dist<<<dim3(32,32,8), 256, DIST_SMEM>>>(x);         // launch 4 -> profiled
    k_topk<<<NPTS, 256>>>();
    k_attn<<<NPTS/2, 128>>>(x);
    k_mlp<<<NPTS/32, 256, MLP_SMEM>>>(w1, w2, g1, b1);
    k_final<<<512, 256>>>(out, g2, b2);
}